// round 10
// baseline (speedup 1.0000x reference)
#include <cuda_runtime.h>
#include <cuda_bf16.h>
#include <math.h>

// Loss = 1.0*n2v + 0.2*wav + 0.01*tv over pred/noisy (64,1,512,512) f32, mask bool.
// Identity: |c - soft_threshold(c, thr)| == min(|c|, thr).
// R10: bulk-async tiles. The kernel was pinned at the LDG issue floor
// (9M LDG.128 x 1.82cyc/SM ~= 58us); cp.async.bulk moves 32KB/instr instead.
// 3-stage pipeline, 16x512 tiles (pred 32KB + mask 32KB or 8KB), 512 thr, grid 152.

#define B_    64
#define H_    512
#define W_    512
#define TROWS 16
#define NT    2048                 // 64 images * 32 strips
#define GRID  152
#define DEPTH 3
#define MAXT  14                   // ceil(2048/152)

#define PRED_BYTES 32768           // 16*512*4
#define STAGE_BYTES 65536
#define OFF_LL1  (DEPTH * STAGE_BYTES)        // 196608, 8 x 256 floats
#define OFF_LL2  (OFF_LL1 + 8192)             // 4 x 128 floats
#define OFF_RED  (OFF_LL2 + 2048)             // 6 x 16 floats
#define OFF_MBAR (OFF_RED + 384)              // 3 x 8B
#define OFF_LAST (OFF_MBAR + 24)              // int flag
#define SMEM_TOTAL (OFF_LAST + 64)

#define THR1 (50.0f / 255.0f)
#define THR2 (25.0f / 255.0f)
#define THR3 (12.5f / 255.0f)

__device__ float    g_part[6][GRID];
__device__ unsigned g_done;        // zero-init; last block resets each replay

__device__ __forceinline__ float clipf(float x) { return fminf(fmaxf(x, 0.0f), 1.0f); }
__device__ __forceinline__ float4 clip4(float4 v) {
    return make_float4(clipf(v.x), clipf(v.y), clipf(v.z), clipf(v.w));
}

__device__ __forceinline__ void mbar_init(unsigned mbar, unsigned cnt) {
    asm volatile("mbarrier.init.shared.b64 [%0], %1;" :: "r"(mbar), "r"(cnt) : "memory");
}
__device__ __forceinline__ void mbar_expect_tx(unsigned mbar, unsigned tx) {
    asm volatile("mbarrier.arrive.expect_tx.shared.b64 _, [%0], %1;"
                 :: "r"(mbar), "r"(tx) : "memory");
}
__device__ __forceinline__ void bulk_g2s(unsigned dst, const void* src,
                                         unsigned bytes, unsigned mbar) {
    asm volatile("cp.async.bulk.shared::cta.global.mbarrier::complete_tx::bytes "
                 "[%0], [%1], %2, [%3];"
                 :: "r"(dst), "l"(src), "r"(bytes), "r"(mbar) : "memory");
}
__device__ __forceinline__ void mbar_wait(unsigned mbar, unsigned parity) {
    asm volatile(
        "{\n\t.reg .pred P;\n\t"
        "W%=:\n\t"
        "mbarrier.try_wait.parity.acquire.cta.shared::cta.b64 P, [%0], %1, 0x989680;\n\t"
        "@P bra D%=;\n\t"
        "bra W%=;\n\t"
        "D%=:\n\t}"
        :: "r"(mbar), "r"(parity) : "memory");
}

template <bool MB>
__device__ __forceinline__ void run_tiles(
    const float* __restrict__ pred, const float* __restrict__ noisy,
    const unsigned char* __restrict__ mask8, const unsigned int* __restrict__ mask32,
    char* smem, unsigned smem_u32, int bk, int tid, int wid, int lane,
    float& a_n2v, float& a_msk, float& a_tv,
    float& a_w1, float& a_w2, float& a_w3)
{
    int tlist[MAXT], n = 0;
    for (int t = bk; t < NT; t += GRID) tlist[n++] = t;

    const unsigned mbar0 = smem_u32 + OFF_MBAR;
    const unsigned mask_tx = MB ? 8192u : 32768u;

    auto issue = [&](int i) {
        if (tid == 0) {
            int tt = tlist[i];
            int s  = i % DEPTH;
            size_t poff = ((size_t)(tt >> 5) * (H_ * W_) + (size_t)(tt & 31) * TROWS * W_);
            unsigned mbar = mbar0 + 8u * s;
            mbar_expect_tx(mbar, PRED_BYTES + mask_tx);
            bulk_g2s(smem_u32 + s * STAGE_BYTES,
                     (const char*)pred + poff * 4, PRED_BYTES, mbar);
            bulk_g2s(smem_u32 + s * STAGE_BYTES + PRED_BYTES,
                     MB ? (const void*)(mask8 + poff)
                        : (const void*)((const char*)mask32 + poff * 4),
                     mask_tx, mbar);
        }
    };

    #pragma unroll 1
    for (int i = 0; i < DEPTH; i++) if (i < n) issue(i);

    float* ll1 = (float*)(smem + OFF_LL1);   // 8 x 256
    float* ll2 = (float*)(smem + OFF_LL2);   // 4 x 128
    const int cw = wid & 3;                  // column quarter 0..3
    const int col0 = 128 * cw + 4 * lane;    // first of 4 owned cols

    #pragma unroll 1
    for (int k = 0; k < n; k++) {
        const int s  = k % DEPTH;
        const int tt = tlist[k];
        const int img = tt >> 5;
        const int r0  = (tt & 31) * TROWS;   // image-local first row
        const size_t img_off = (size_t)img * (H_ * W_);

        mbar_wait(mbar0 + 8u * s, (unsigned)((k / DEPTH) & 1));

        const float*  sp  = (const float*)(smem + s * STAGE_BYTES);
        const float4* sp4 = (const float4*)sp;
        const unsigned* mw = (const unsigned*)(smem + s * STAGE_BYTES + PRED_BYTES);
        const uint4*   mw4 = (const uint4*)mw;

        // ===== main pass: 2 rounds; warp handles row pair p, cols col0..col0+3 =====
        #pragma unroll
        for (int j = 0; j < 2; j++) {
            const int p  = (wid >> 2) + 4 * j;     // pair 0..7
            const int rA = 2 * p, rB = 2 * p + 1;
            const int idxA = rA * 128 + 32 * cw + lane;   // float4 index in 512-wide row

            float4 t  = clip4(sp4[idxA]);
            float4 bo = clip4(sp4[idxA + 128]);

            // next row for vertical TV (row rB+1)
            float4 nx;
            float vm = 1.f;
            if (p < 7) {
                nx = clip4(sp4[idxA + 256]);
            } else if (r0 + TROWS < H_) {
                nx = clip4(__ldg((const float4*)(pred + img_off
                         + (size_t)(r0 + TROWS) * W_ + col0)));
            } else {
                nx = make_float4(0.f, 0.f, 0.f, 0.f);
                vm = 0.f;
            }

            // horizontal boundary px (col0+4) via shfl; lane31 reads smem scalar
            float ntA = __shfl_down_sync(0xFFFFFFFFu, t.x, 1);
            float ntB = __shfl_down_sync(0xFFFFFFFFu, bo.x, 1);
            float hm = 1.f;
            if (lane == 31) {
                if (cw < 3) {
                    ntA = clipf(sp[rA * W_ + col0 + 4]);
                    ntB = clipf(sp[rB * W_ + col0 + 4]);
                } else {
                    hm = 0.f;
                }
            }

            a_tv += fabsf(t.y - t.x) + fabsf(t.z - t.y) + fabsf(t.w - t.z)
                  + hm * fabsf(ntA - t.w)
                  + fabsf(bo.y - bo.x) + fabsf(bo.z - bo.y) + fabsf(bo.w - bo.z)
                  + hm * fabsf(ntB - bo.w)
                  + fabsf(bo.x - t.x) + fabsf(bo.y - t.y)
                  + fabsf(bo.z - t.z) + fabsf(bo.w - t.w)
                  + vm * (fabsf(nx.x - bo.x) + fabsf(nx.y - bo.y)
                        + fabsf(nx.z - bo.z) + fabsf(nx.w - bo.w));

            // DWT level 1 (finest => THR3): 2 outputs at ll1[p][col0/2 .. +1]
            float s0 = t.x + t.y, t0 = bo.x + bo.y, u0 = t.x - t.y, v0 = bo.x - bo.y;
            float ch0 = (s0 - t0) * 0.5f, cv0 = (u0 + v0) * 0.5f, cd0 = (u0 - v0) * 0.5f;
            float s1 = t.z + t.w, t1 = bo.z + bo.w, u1 = t.z - t.w, v1 = bo.z - bo.w;
            float ch1 = (s1 - t1) * 0.5f, cv1 = (u1 + v1) * 0.5f, cd1 = (u1 - v1) * 0.5f;
            a_w3 += fminf(fabsf(ch0), THR3) + fminf(fabsf(cv0), THR3) + fminf(fabsf(cd0), THR3)
                  + fminf(fabsf(ch1), THR3) + fminf(fabsf(cv1), THR3) + fminf(fabsf(cd1), THR3);
            ((float2*)ll1)[p * 128 + 32 * cw + lane] =
                make_float2((s0 + t0) * 0.5f, (s1 + t1) * 0.5f);

            // n2v from smem mask + sparse noisy gather
            float mA0, mA1, mA2, mA3, mB0, mB1, mB2, mB3;
            bool anyA, anyB;
            if (MB) {
                unsigned wA = mw[idxA];            // 4 mask bytes, same index math
                unsigned wB = mw[idxA + 128];
                anyA = wA != 0u; anyB = wB != 0u;
                mA0 = (wA & 0x000000FFu) ? 1.f : 0.f; mA1 = (wA & 0x0000FF00u) ? 1.f : 0.f;
                mA2 = (wA & 0x00FF0000u) ? 1.f : 0.f; mA3 = (wA & 0xFF000000u) ? 1.f : 0.f;
                mB0 = (wB & 0x000000FFu) ? 1.f : 0.f; mB1 = (wB & 0x0000FF00u) ? 1.f : 0.f;
                mB2 = (wB & 0x00FF0000u) ? 1.f : 0.f; mB3 = (wB & 0xFF000000u) ? 1.f : 0.f;
            } else {
                uint4 wA = mw4[idxA];
                uint4 wB = mw4[idxA + 128];
                anyA = (wA.x | wA.y | wA.z | wA.w) != 0u;
                anyB = (wB.x | wB.y | wB.z | wB.w) != 0u;
                mA0 = wA.x ? 1.f : 0.f; mA1 = wA.y ? 1.f : 0.f;
                mA2 = wA.z ? 1.f : 0.f; mA3 = wA.w ? 1.f : 0.f;
                mB0 = wB.x ? 1.f : 0.f; mB1 = wB.y ? 1.f : 0.f;
                mB2 = wB.z ? 1.f : 0.f; mB3 = wB.w ? 1.f : 0.f;
            }
            a_msk += (mA0 + mA1) + (mA2 + mA3) + (mB0 + mB1) + (mB2 + mB3);
            if (anyA) {
                float4 nv = __ldg((const float4*)(noisy + img_off
                               + (size_t)(r0 + rA) * W_ + col0));
                a_n2v += fabsf(t.x - nv.x) * mA0 + fabsf(t.y - nv.y) * mA1
                       + fabsf(t.z - nv.z) * mA2 + fabsf(t.w - nv.w) * mA3;
            }
            if (anyB) {
                float4 nv = __ldg((const float4*)(noisy + img_off
                               + (size_t)(r0 + rB) * W_ + col0));
                a_n2v += fabsf(bo.x - nv.x) * mB0 + fabsf(bo.y - nv.y) * mB1
                       + fabsf(bo.z - nv.z) * mB2 + fabsf(bo.w - nv.w) * mB3;
            }
        }
        __syncthreads();                     // stage s fully consumed; ll1 complete

        if (k + DEPTH < n) issue(k + DEPTH); // refill stage s behind the sync

        // ===== DWT level 2: 8x256 -> 4x128 (THR2), one output per thread =====
        {
            int ot = tid >> 7, oc = tid & 127;
            float2 tp = ((const float2*)ll1)[(2 * ot) * 128 + oc];
            float2 bo = ((const float2*)ll1)[(2 * ot + 1) * 128 + oc];
            float s0 = tp.x + tp.y, t0 = bo.x + bo.y, u0 = tp.x - tp.y, v0 = bo.x - bo.y;
            float ch = (s0 - t0) * 0.5f, cv = (u0 + v0) * 0.5f, cd = (u0 - v0) * 0.5f;
            a_w2 += fminf(fabsf(ch), THR2) + fminf(fabsf(cv), THR2) + fminf(fabsf(cd), THR2);
            ll2[ot * 128 + oc] = (s0 + t0) * 0.5f;
        }
        __syncthreads();

        // ===== DWT level 3: 4x128 -> 2x64 details (THR1) =====
        if (tid < 128) {
            int i = tid >> 6, jj = tid & 63;
            float2 tp = ((const float2*)ll2)[(2 * i) * 64 + jj];
            float2 bo = ((const float2*)ll2)[(2 * i + 1) * 64 + jj];
            float s0 = tp.x + tp.y, t0 = bo.x + bo.y, u0 = tp.x - tp.y, v0 = bo.x - bo.y;
            float ch = (s0 - t0) * 0.5f, cv = (u0 + v0) * 0.5f, cd = (u0 - v0) * 0.5f;
            a_w1 += fminf(fabsf(ch), THR1) + fminf(fabsf(cv), THR1) + fminf(fabsf(cd), THR1);
        }
    }
}

__global__ __launch_bounds__(512)
void loss_kernel(const float* __restrict__ pred,
                 const float* __restrict__ noisy,
                 const unsigned char* __restrict__ mask8,
                 const unsigned int* __restrict__ mask32,
                 float* __restrict__ out) {
    extern __shared__ char smem[];
    unsigned smem_u32;
    asm("{ .reg .u64 t; cvta.to.shared.u64 t, %1; cvt.u32.u64 %0, t; }"
        : "=r"(smem_u32) : "l"(smem));

    const int tid  = threadIdx.x;
    const int wid  = tid >> 5;
    const int lane = tid & 31;
    const int bk   = blockIdx.x;
    int* amLast = (int*)(smem + OFF_LAST);

    // mask layout probe: first 2KB (L2-hot across blocks). Byte-packed bools
    // yield words outside {0,1,0x3F800000}; int32/f32 encodings never do.
    unsigned pw = mask32[tid];
    int bad = (pw != 0u && pw != 1u && pw != 0x3F800000u) ? 1 : 0;
    const int mask_is_byte = __syncthreads_or(bad);

    if (tid == 0) {
        #pragma unroll
        for (int s = 0; s < DEPTH; s++) mbar_init(smem_u32 + OFF_MBAR + 8u * s, 1);
    }
    __syncthreads();

    float a_n2v = 0.f, a_msk = 0.f, a_tv = 0.f;
    float a_w1 = 0.f, a_w2 = 0.f, a_w3 = 0.f;

    if (mask_is_byte)
        run_tiles<true >(pred, noisy, mask8, mask32, smem, smem_u32, bk, tid, wid, lane,
                         a_n2v, a_msk, a_tv, a_w1, a_w2, a_w3);
    else
        run_tiles<false>(pred, noisy, mask8, mask32, smem, smem_u32, bk, tid, wid, lane,
                         a_n2v, a_msk, a_tv, a_w1, a_w2, a_w3);

    // ===== block reduce (16 warps), write partials =====
    float* red = (float*)(smem + OFF_RED);   // [6][16]
    float vals[6] = {a_n2v, a_msk, a_w1, a_w2, a_w3, a_tv};
    #pragma unroll
    for (int k = 0; k < 6; k++) {
        float s = vals[k];
        #pragma unroll
        for (int o = 16; o > 0; o >>= 1) s += __shfl_down_sync(0xFFFFFFFFu, s, o);
        if (lane == 0) red[k * 16 + wid] = s;
    }
    __syncthreads();
    if (tid == 0) {
        #pragma unroll
        for (int k = 0; k < 6; k++) {
            float s = 0.f;
            #pragma unroll
            for (int w = 0; w < 16; w++) s += red[k * 16 + w];
            g_part[k][bk] = s;
        }
        __threadfence();
        unsigned prev = atomicAdd(&g_done, 1u);
        *amLast = (prev == GRID - 1);
    }
    __syncthreads();

    // ===== last block: fused finalize =====
    if (*amLast) {
        double acc[6] = {0, 0, 0, 0, 0, 0};
        if (tid < GRID) {
            #pragma unroll
            for (int k = 0; k < 6; k++)
                acc[k] += (double)((volatile float*)g_part[k])[tid];
        }
        double* sred = (double*)(smem + OFF_RED);  // reuse (needs 6*16*8=768B... use ll1)
        sred = (double*)(smem + OFF_LL1);
        #pragma unroll
        for (int k = 0; k < 6; k++) {
            #pragma unroll
            for (int o = 16; o > 0; o >>= 1)
                acc[k] += __shfl_down_sync(0xFFFFFFFFu, acc[k], o);
            if (lane == 0) sred[k * 16 + wid] = acc[k];
        }
        __syncthreads();
        if (tid == 0) {
            double t[6];
            #pragma unroll
            for (int k = 0; k < 6; k++) {
                double s = 0.0;
                #pragma unroll
                for (int w = 0; w < 16; w++) s += sred[k * 16 + w];
                t[k] = s;
            }
            double n2v = t[0] / fmax(t[1], 1.0);
            double wav = 1.0       * (t[2] / (3.0 * B_ * 64.0  * 64.0))
                       + (1.0/2.0) * (t[3] / (3.0 * B_ * 128.0 * 128.0))
                       + (1.0/3.0) * (t[4] / (3.0 * B_ * 256.0 * 256.0));
            double tv  = t[5] / ((double)B_ * 511.0 * 512.0);
            out[0] = (float)(1.0 * n2v + 0.2 * wav + 0.01 * tv);
            g_done = 0;   // reset for next graph replay
        }
    }
}

extern "C" void kernel_launch(void* const* d_in, const int* in_sizes, int n_in,
                              void* d_out, int out_size) {
    const float* pred  = (const float*)d_in[0];
    const float* noisy = (const float*)d_in[1];
    const void*  mask  = d_in[2];
    float* out = (float*)d_out;

    static int attr_set = 0;
    if (!attr_set) {
        cudaFuncSetAttribute(loss_kernel,
                             cudaFuncAttributeMaxDynamicSharedMemorySize, SMEM_TOTAL);
        attr_set = 1;
    }
    loss_kernel<<<GRID, 512, SMEM_TOTAL>>>(pred, noisy,
                                           (const unsigned char*)mask,
                                           (const unsigned int*)mask,
                                           out);
}

// round 11
// speedup vs baseline: 1.3304x; 1.3304x over previous
#include <cuda_runtime.h>
#include <cuda_bf16.h>
#include <math.h>

// Loss = 1.0*n2v + 0.2*wav + 0.01*tv over pred/noisy (64,1,512,512) f32, mask bool.
// Identity: |c - soft_threshold(c, thr)| == min(|c|, thr).
// R11: compute-latency attack. 8x512 strips (contiguous -> 1D bulk copy incl.
// 9th halo row), thread owns a 4x4 block so DWT L1+L2 are register-local and
// L3 is 3 shfl_xor; zero intra-tile block barriers. 3 CTAs/SM, DEPTH-2 bulk
// pipeline. Prior rounds were per-tile compute-bound (load:compute 1:2.6).

#define B_    64
#define H_    512
#define W_    512
#define NT    4096                 // 64 images * 64 strips of 8 rows
#define GRID  456                  // 3 CTAs/SM * 152
#define MAXT  9
#define DEPTH 2

#define STAGE_BYTES 34816          // pred 9*2048=18432 + mask<=16384
#define OFF_MASK    18432
#define OFF_RED     (2 * STAGE_BYTES)      // float[6][8]
#define OFF_SRED    (OFF_RED + 192)        // double[6][8]
#define OFF_MBAR    (OFF_SRED + 384)       // 2 x 8B
#define OFF_LAST    (OFF_MBAR + 16)
#define SMEM_TOTAL  (OFF_LAST + 32)

#define THR1 (50.0f / 255.0f)
#define THR2 (25.0f / 255.0f)
#define THR3 (12.5f / 255.0f)

__device__ float    g_part[6][GRID];
__device__ unsigned g_done;        // zero-init; last block resets each replay

__device__ __forceinline__ float clipf(float x) { return fminf(fmaxf(x, 0.0f), 1.0f); }
__device__ __forceinline__ float4 clip4(float4 v) {
    return make_float4(clipf(v.x), clipf(v.y), clipf(v.z), clipf(v.w));
}

__device__ __forceinline__ void mbar_init(unsigned mbar, unsigned cnt) {
    asm volatile("mbarrier.init.shared.b64 [%0], %1;" :: "r"(mbar), "r"(cnt) : "memory");
}
__device__ __forceinline__ void mbar_expect_tx(unsigned mbar, unsigned tx) {
    asm volatile("mbarrier.arrive.expect_tx.shared.b64 _, [%0], %1;"
                 :: "r"(mbar), "r"(tx) : "memory");
}
__device__ __forceinline__ void bulk_g2s(unsigned dst, const void* src,
                                         unsigned bytes, unsigned mbar) {
    asm volatile("cp.async.bulk.shared::cta.global.mbarrier::complete_tx::bytes "
                 "[%0], [%1], %2, [%3];"
                 :: "r"(dst), "l"(src), "r"(bytes), "r"(mbar) : "memory");
}
__device__ __forceinline__ void mbar_wait(unsigned mbar, unsigned parity) {
    asm volatile(
        "{\n\t.reg .pred P;\n\t"
        "W%=:\n\t"
        "mbarrier.try_wait.parity.acquire.cta.shared::cta.b64 P, [%0], %1, 0x989680;\n\t"
        "@P bra D%=;\n\t"
        "bra W%=;\n\t"
        "D%=:\n\t}"
        :: "r"(mbar), "r"(parity) : "memory");
}

template <bool MB>
__device__ __forceinline__ void run_tiles(
    const float* __restrict__ pred, const float* __restrict__ noisy,
    const unsigned char* __restrict__ mask8, const unsigned int* __restrict__ mask32,
    char* smem, unsigned smem_u32, int bk, int tid, int wid, int lane,
    float& a_n2v, float& a_msk, float& a_tv,
    float& a_w1, float& a_w2, float& a_w3)
{
    int tlist[MAXT], n = 0;
    for (int t = bk; t < NT; t += GRID) tlist[n++] = t;
    const unsigned mbar0 = smem_u32 + OFF_MBAR;

    auto issue = [&](int i) {
        if (tid == 0) {
            int tt = tlist[i], s = i & 1;
            int img = tt >> 6, strip = tt & 63;
            size_t off = (size_t)img * (H_ * W_) + (size_t)strip * 8 * W_;
            unsigned prows  = (strip == 63) ? 8u : 9u;   // 9th row = vertical halo
            unsigned pbytes = prows * 2048u;
            unsigned mbytes = MB ? 4096u : 16384u;
            unsigned mbar = mbar0 + 8u * s;
            mbar_expect_tx(mbar, pbytes + mbytes);
            bulk_g2s(smem_u32 + s * STAGE_BYTES, (const char*)pred + off * 4, pbytes, mbar);
            bulk_g2s(smem_u32 + s * STAGE_BYTES + OFF_MASK,
                     MB ? (const void*)(mask8 + off)
                        : (const void*)((const char*)mask32 + off * 4),
                     mbytes, mbar);
        }
    };
    issue(0);
    if (n > 1) issue(1);

    // thread owns a 4x4 pixel block: cols colw..colw+3, rows rowb..rowb+3
    const int cg   = lane & 15;          // col group within warp (16 x 4 = 64 cols)
    const int rg   = lane >> 4;          // row group 0/1 (rows 0-3 / 4-7)
    const int colw = 64 * wid + 4 * cg;
    const int fidx = colw >> 2;
    const int rowb = 4 * rg;
    const float hmv  = (cg == 15 && wid == 7) ? 0.f : 1.f;
    const int   hoff = (cg == 15 && wid == 7) ? colw + 3 : colw + 4;  // in-bounds

    #pragma unroll 1
    for (int k = 0; k < n; k++) {
        const int s = k & 1;
        mbar_wait(mbar0 + 8u * s, (unsigned)((k >> 1) & 1));

        const int tt   = tlist[k];
        const int img  = tt >> 6;
        const int r0   = (tt & 63) * 8;
        const size_t img_off = (size_t)img * (H_ * W_);
        const float*    sp  = (const float*)(smem + s * STAGE_BYTES);
        const float4*   sp4 = (const float4*)sp;
        const unsigned* mwp = (const unsigned*)(smem + s * STAGE_BYTES + OFF_MASK);
        const uint4*    mw4 = (const uint4*)mwp;

        float4 cur = clip4(sp4[rowb * 128 + fidx]);
        float ll1v[2][2];

        #pragma unroll
        for (int i = 0; i < 4; i++) {
            const int lr = rowb + i;
            float4 nxt = clip4(sp4[(lr + 1) * 128 + fidx]);
            float  hn  = clipf(sp[lr * 512 + hoff]);

            // TV horizontal (always valid) + vertical (skip at image edge:
            // halo row may hold stale smem — must branch, not multiply)
            a_tv += fabsf(cur.y - cur.x) + fabsf(cur.z - cur.y) + fabsf(cur.w - cur.z)
                  + hmv * fabsf(hn - cur.w);
            if (r0 + lr != 511)
                a_tv += fabsf(nxt.x - cur.x) + fabsf(nxt.y - cur.y)
                      + fabsf(nxt.z - cur.z) + fabsf(nxt.w - cur.w);

            // DWT level 1 on even i (pair lr, lr+1) — 2 col-blocks, register-local
            if ((i & 1) == 0) {
                float s0 = cur.x + cur.y, t0 = nxt.x + nxt.y;
                float u0 = cur.x - cur.y, v0 = nxt.x - nxt.y;
                float ch0 = (s0 - t0) * 0.5f, cv0 = (u0 + v0) * 0.5f, cd0 = (u0 - v0) * 0.5f;
                float s1 = cur.z + cur.w, t1 = nxt.z + nxt.w;
                float u1 = cur.z - cur.w, v1 = nxt.z - nxt.w;
                float ch1 = (s1 - t1) * 0.5f, cv1 = (u1 + v1) * 0.5f, cd1 = (u1 - v1) * 0.5f;
                a_w3 += fminf(fabsf(ch0), THR3) + fminf(fabsf(cv0), THR3) + fminf(fabsf(cd0), THR3)
                      + fminf(fabsf(ch1), THR3) + fminf(fabsf(cv1), THR3) + fminf(fabsf(cd1), THR3);
                ll1v[i >> 1][0] = (s0 + t0) * 0.5f;
                ll1v[i >> 1][1] = (s1 + t1) * 0.5f;
            }

            // n2v: mask from stage, sparse noisy gather
            float m0, m1, m2, m3;
            bool any;
            if (MB) {
                unsigned w = mwp[lr * 128 + fidx];
                any = (w != 0u);
                m0 = (w & 0x000000FFu) ? 1.f : 0.f;
                m1 = (w & 0x0000FF00u) ? 1.f : 0.f;
                m2 = (w & 0x00FF0000u) ? 1.f : 0.f;
                m3 = (w & 0xFF000000u) ? 1.f : 0.f;
            } else {
                uint4 w = mw4[lr * 128 + fidx];
                any = (w.x | w.y | w.z | w.w) != 0u;
                m0 = w.x ? 1.f : 0.f; m1 = w.y ? 1.f : 0.f;
                m2 = w.z ? 1.f : 0.f; m3 = w.w ? 1.f : 0.f;
            }
            a_msk += (m0 + m1) + (m2 + m3);
            if (any) {
                float4 nv = __ldg((const float4*)(noisy + img_off
                               + (size_t)(r0 + lr) * W_ + colw));
                a_n2v += fabsf(cur.x - nv.x) * m0 + fabsf(cur.y - nv.y) * m1
                       + fabsf(cur.z - nv.z) * m2 + fabsf(cur.w - nv.w) * m3;
            }
            cur = nxt;
        }

        // DWT level 2 (thread-local 2x2 of LL1)
        float x;
        {
            float a = ll1v[0][0], b = ll1v[0][1], c = ll1v[1][0], d = ll1v[1][1];
            float s0 = a + b, t0 = c + d, u0 = a - b, v0 = c - d;
            float ch = (s0 - t0) * 0.5f, cv = (u0 + v0) * 0.5f, cd = (u0 - v0) * 0.5f;
            a_w2 += fminf(fabsf(ch), THR2) + fminf(fabsf(cv), THR2) + fminf(fabsf(cd), THR2);
            x = (s0 + t0) * 0.5f;           // LL2(rg, cg)
        }
        // DWT level 3 via shfl: cols pair lane^1, rows pair lane^16
        {
            float y  = __shfl_xor_sync(0xFFFFFFFFu, x, 1);
            float z  = __shfl_xor_sync(0xFFFFFFFFu, x, 16);
            float zy = __shfl_xor_sync(0xFFFFFFFFu, y, 16);
            if (rg == 0 && (cg & 1) == 0) {   // 8 lanes own one L3 block each
                float s3 = x + y, t3 = z + zy, u3 = x - y, v3 = z - zy;
                float ch = (s3 - t3) * 0.5f, cv = (u3 + v3) * 0.5f, cd = (u3 - v3) * 0.5f;
                a_w1 += fminf(fabsf(ch), THR1) + fminf(fabsf(cv), THR1) + fminf(fabsf(cd), THR1);
            }
        }

        __syncthreads();                    // stage s consumed by all warps
        if (k + DEPTH < n) issue(k + DEPTH);
    }
}

__global__ __launch_bounds__(256, 3)
void loss_kernel(const float* __restrict__ pred,
                 const float* __restrict__ noisy,
                 const unsigned char* __restrict__ mask8,
                 const unsigned int* __restrict__ mask32,
                 float* __restrict__ out) {
    extern __shared__ char smem[];
    unsigned smem_u32;
    asm("{ .reg .u64 t; cvta.to.shared.u64 t, %1; cvt.u32.u64 %0, t; }"
        : "=r"(smem_u32) : "l"(smem));

    const int tid  = threadIdx.x;
    const int wid  = tid >> 5;
    const int lane = tid & 31;
    const int bk   = blockIdx.x;
    int* amLast = (int*)(smem + OFF_LAST);

    // mask layout probe: first 512 words (2KB, L2-hot across blocks). Byte-packed
    // bools yield words outside {0,1,0x3F800000}; int32/f32 encodings never do.
    unsigned pw0 = mask32[tid], pw1 = mask32[tid + 256];
    int bad = ((pw0 != 0u && pw0 != 1u && pw0 != 0x3F800000u) ||
               (pw1 != 0u && pw1 != 1u && pw1 != 0x3F800000u)) ? 1 : 0;
    const int mask_is_byte = __syncthreads_or(bad);

    if (tid == 0) {
        mbar_init(smem_u32 + OFF_MBAR, 1);
        mbar_init(smem_u32 + OFF_MBAR + 8, 1);
    }
    __syncthreads();

    float a_n2v = 0.f, a_msk = 0.f, a_tv = 0.f;
    float a_w1 = 0.f, a_w2 = 0.f, a_w3 = 0.f;

    if (mask_is_byte)
        run_tiles<true >(pred, noisy, mask8, mask32, smem, smem_u32, bk, tid, wid, lane,
                         a_n2v, a_msk, a_tv, a_w1, a_w2, a_w3);
    else
        run_tiles<false>(pred, noisy, mask8, mask32, smem, smem_u32, bk, tid, wid, lane,
                         a_n2v, a_msk, a_tv, a_w1, a_w2, a_w3);

    // ===== block reduce (8 warps), write partials =====
    float* red = (float*)(smem + OFF_RED);
    float vals[6] = {a_n2v, a_msk, a_w1, a_w2, a_w3, a_tv};
    #pragma unroll
    for (int k = 0; k < 6; k++) {
        float sv = vals[k];
        #pragma unroll
        for (int o = 16; o > 0; o >>= 1) sv += __shfl_down_sync(0xFFFFFFFFu, sv, o);
        if (lane == 0) red[k * 8 + wid] = sv;
    }
    __syncthreads();
    if (tid == 0) {
        #pragma unroll
        for (int k = 0; k < 6; k++) {
            float sv = 0.f;
            #pragma unroll
            for (int w = 0; w < 8; w++) sv += red[k * 8 + w];
            g_part[k][bk] = sv;
        }
        __threadfence();
        unsigned prev = atomicAdd(&g_done, 1u);
        *amLast = (prev == GRID - 1);
    }
    __syncthreads();

    // ===== last block: fused finalize =====
    if (*amLast) {
        double acc[6] = {0, 0, 0, 0, 0, 0};
        for (int i = tid; i < GRID; i += 256) {
            #pragma unroll
            for (int k = 0; k < 6; k++)
                acc[k] += (double)((volatile float*)g_part[k])[i];
        }
        double* sred = (double*)(smem + OFF_SRED);
        #pragma unroll
        for (int k = 0; k < 6; k++) {
            #pragma unroll
            for (int o = 16; o > 0; o >>= 1)
                acc[k] += __shfl_down_sync(0xFFFFFFFFu, acc[k], o);
            if (lane == 0) sred[k * 8 + wid] = acc[k];
        }
        __syncthreads();
        if (tid == 0) {
            double t[6];
            #pragma unroll
            for (int k = 0; k < 6; k++) {
                double sv = 0.0;
                #pragma unroll
                for (int w = 0; w < 8; w++) sv += sred[k * 8 + w];
                t[k] = sv;
            }
            double n2v = t[0] / fmax(t[1], 1.0);
            double wav = 1.0       * (t[2] / (3.0 * B_ * 64.0  * 64.0))
                       + (1.0/2.0) * (t[3] / (3.0 * B_ * 128.0 * 128.0))
                       + (1.0/3.0) * (t[4] / (3.0 * B_ * 256.0 * 256.0));
            double tv  = t[5] / ((double)B_ * 511.0 * 512.0);
            out[0] = (float)(1.0 * n2v + 0.2 * wav + 0.01 * tv);
            g_done = 0;   // reset for next graph replay
        }
    }
}

extern "C" void kernel_launch(void* const* d_in, const int* in_sizes, int n_in,
                              void* d_out, int out_size) {
    const float* pred  = (const float*)d_in[0];
    const float* noisy = (const float*)d_in[1];
    const void*  mask  = d_in[2];
    float* out = (float*)d_out;

    static int attr_set = 0;
    if (!attr_set) {
        cudaFuncSetAttribute(loss_kernel,
                             cudaFuncAttributeMaxDynamicSharedMemorySize, SMEM_TOTAL);
        attr_set = 1;
    }
    loss_kernel<<<GRID, 256, SMEM_TOTAL>>>(pred, noisy,
                                           (const unsigned char*)mask,
                                           (const unsigned int*)mask,
                                           out);
}